// round 7
// baseline (speedup 1.0000x reference)
#include <cuda_runtime.h>
#include <cuda_bf16.h>
#include <cstdint>

// ---------------------------------------------------------------------------
// GromovWassersteinEmbedding — GB300 sm_103a (target sm_103 => mma.sync path)
//
//   d_gw = f1·rs + f2·csm - 2*<T, Cs T Ct>
//   Cs = c0·J + diag(a) + As,  Ct = c0·J + diag(b) + Bs   (As,Bs bf16 off-diag)
//   <T,CsTCt> = c0²S² + c0·rsᵀDs rs + c0·csmᵀDt csm + <T, Ds T Dt>
//   X = Ds T = (As@T)_bf16-tensor + diag(a)·T (fp32 epilogue)
//   <T, Ds T Dt> = <T, X@Bs> (GEMM2 fused) + Σ T∘X·b (GEMM1 epilogue)
//   d_w = sum(cost_st .* T) fused;  reg = sims + orths.
//   GEMM mainloop: ldmatrix.x4 fragments + 4-stage cp.async pipeline.
// ---------------------------------------------------------------------------

using bf16 = __nv_bfloat16;
using bf162 = __nv_bfloat162;

constexpr int NV = 4096;
constexpr int DV = 128;
constexpr float C0F = 0.99326205f;   // ~ 1 - exp(-5); identity exact for any c0

__device__ float  g_embs1[NV * DV];
__device__ float  g_embs2[NV * DV];
__device__ bf16   g_eh1[NV * DV];          // bf16 embs for gram mma
__device__ bf16   g_eh2[NV * DV];
__device__ float  g_e1[NV];
__device__ float  g_e2[NV];
__device__ bf16   g_cs[(size_t)NV * NV];   // As (off-diag, bf16, symmetric)
__device__ bf16   g_ct[(size_t)NV * NV];   // Bs
__device__ bf16   g_Tt[(size_t)NV * NV];   // trans^T bf16
__device__ bf16   g_X [(size_t)NV * NV];   // X = Ds T, bf16
__device__ float  g_da[NV];                // diag of Ds (fp32)
__device__ float  g_db[NV];                // diag of Dt
__device__ float  g_f1[NV];
__device__ float  g_f2[NV];
__device__ float  g_rs[NV];
__device__ float  g_csm[NV];
__device__ double g_acc[16];
// acc: 0 reg_s, 1 reg_t, 2 orth1, 3 orth2, 4 d_w, 5 <T, X@Bs>,
//      6 rs'Ds rs, 7 csm'Dt csm, 8 sum T∘X·b

// ------------------------------- helpers -----------------------------------
__device__ __forceinline__ uint32_t smem_u32(const void* p) {
    uint32_t a;
    asm("{ .reg .u64 t; cvta.to.shared.u64 t, %1; cvt.u32.u64 %0, t; }" : "=r"(a) : "l"(p));
    return a;
}
#define CP16(dst, src) \
    asm volatile("cp.async.cg.shared.global [%0], [%1], 16;" :: "r"(dst), "l"(src))
#define CP_COMMIT() asm volatile("cp.async.commit_group;" ::: "memory")
#define CP_WAIT3()  asm volatile("cp.async.wait_group 3;" ::: "memory")

__device__ __forceinline__ void mma_bf16(float c[4], const uint32_t a[4], const uint32_t b[2]) {
    asm volatile("mma.sync.aligned.m16n8k16.row.col.f32.bf16.bf16.f32 "
                 "{%0,%1,%2,%3}, {%4,%5,%6,%7}, {%8,%9}, {%0,%1,%2,%3};"
                 : "+f"(c[0]), "+f"(c[1]), "+f"(c[2]), "+f"(c[3])
                 : "r"(a[0]), "r"(a[1]), "r"(a[2]), "r"(a[3]),
                   "r"(b[0]), "r"(b[1]));
}
__device__ __forceinline__ void ldsm_x4(uint32_t r[4], uint32_t addr) {
    asm volatile("ldmatrix.sync.aligned.m8n8.x4.shared.b16 {%0,%1,%2,%3}, [%4];"
                 : "=r"(r[0]), "=r"(r[1]), "=r"(r[2]), "=r"(r[3]) : "r"(addr));
}

// ---------------------------------------------------------------------------
__global__ void k_init() {
    int i = blockIdx.x * blockDim.x + threadIdx.x;
    if (i < NV) { g_f1[i] = 0.f; g_f2[i] = 0.f; g_csm[i] = 0.f; }
    if (i < 16) g_acc[i] = 0.0;
}

__global__ void k_gather(const int* __restrict__ idx1, const int* __restrict__ idx2,
                         const float* __restrict__ w1, const float* __restrict__ w2) {
    int b = blockIdx.x;
    int table = b >> 12;
    int row = b & (NV - 1);
    const int* __restrict__ idx = table ? idx2 : idx1;
    const float* __restrict__ w = table ? w2 : w1;
    float* embs = table ? g_embs2 : g_embs1;
    bf16* embh = table ? g_eh2 : g_eh1;
    float* e = table ? g_e2 : g_e1;
    int t = threadIdx.x;
    float v = w[(size_t)idx[row] * DV + t];
    embs[row * DV + t] = v;
    embh[row * DV + t] = __float2bfloat16(v);
    float s = v * v;
    #pragma unroll
    for (int o = 16; o; o >>= 1) s += __shfl_down_sync(0xffffffffu, s, o);
    __shared__ float ws[4];
    if ((t & 31) == 0) ws[t >> 5] = s;
    __syncthreads();
    if (t == 0) e[row] = sqrtf(ws[0] + ws[1] + ws[2] + ws[3]);
}

// ---------------------------------------------------------------------------
// Cost kernels with tensor-core gram: 64x64 tile/block, 8 warps (2m x 4n).
// ---------------------------------------------------------------------------
template<bool SELF>
__global__ __launch_bounds__(256) void k_cost_mma(int table,
        const float* __restrict__ aux, const float* __restrict__ mu) {
    const bf16* __restrict__ embA = (SELF && table) ? g_eh2 : g_eh1;
    const bf16* __restrict__ embB = SELF ? embA : g_eh2;
    const float* __restrict__ eA  = (SELF && table) ? g_e2 : g_e1;
    const float* __restrict__ eB  = SELF ? eA : g_e2;
    bf16*  __restrict__ cost = table ? g_ct : g_cs;
    float* __restrict__ diag = table ? g_db : g_da;
    float* __restrict__ fout = table ? g_f2 : g_f1;

    __shared__ __align__(16) char smA[64 * 272];
    __shared__ __align__(16) char smB[64 * 272];
    __shared__ float red[256];

    int tid = threadIdx.x, wid = tid >> 5, lane = tid & 31;
    int g = lane >> 2, tig = lane & 3;
    int wm = wid >> 2, wn = wid & 3;
    int i0 = blockIdx.y * 64, j0 = blockIdx.x * 64;

    #pragma unroll
    for (int q = 0; q < 4; q++) {
        int idx = tid + 256 * q;           // 0..1023
        int row = idx >> 4, c16 = idx & 15;
        *(uint4*)(smA + row * 272 + c16 * 16) =
            *(const uint4*)&embA[(size_t)(i0 + row) * DV + c16 * 8];
        *(uint4*)(smB + row * 272 + c16 * 16) =
            *(const uint4*)&embB[(size_t)(j0 + row) * DV + c16 * 8];
    }
    __syncthreads();

    float acc[2][2][4];
    #pragma unroll
    for (int mi = 0; mi < 2; mi++)
        #pragma unroll
        for (int ni = 0; ni < 2; ni++)
            #pragma unroll
            for (int q = 0; q < 4; q++) acc[mi][ni][q] = 0.f;

    #pragma unroll
    for (int k = 0; k < 8; k++) {
        int kb = k * 32;
        uint32_t afr[2][4], bfr[2][2];
        #pragma unroll
        for (int mi = 0; mi < 2; mi++) {
            const char* ar0 = smA + (wm * 32 + mi * 16 + g) * 272 + kb + tig * 4;
            const char* ar1 = ar0 + 8 * 272;
            afr[mi][0] = *(const uint32_t*)ar0;
            afr[mi][1] = *(const uint32_t*)ar1;
            afr[mi][2] = *(const uint32_t*)(ar0 + 16);
            afr[mi][3] = *(const uint32_t*)(ar1 + 16);
        }
        #pragma unroll
        for (int ni = 0; ni < 2; ni++) {
            const char* br = smB + (wn * 16 + ni * 8 + g) * 272 + kb + tig * 4;
            bfr[ni][0] = *(const uint32_t*)br;
            bfr[ni][1] = *(const uint32_t*)(br + 16);
        }
        #pragma unroll
        for (int mi = 0; mi < 2; mi++)
            #pragma unroll
            for (int ni = 0; ni < 2; ni++)
                mma_bf16(acc[mi][ni], afr[mi], bfr[ni]);
    }

    const float scale = SELF ? 5.0f : 1.0f;
    float sloc = 0.f;
    #pragma unroll
    for (int mi = 0; mi < 2; mi++) {
        int r0 = i0 + wm * 32 + mi * 16 + g;
        int r1 = r0 + 8;
        float ei0 = eA[r0], ei1 = eA[r1];
        float f0 = 0.f, f1v = 0.f;
        #pragma unroll
        for (int ni = 0; ni < 2; ni++) {
            int col = j0 + wn * 16 + ni * 8 + 2 * tig;
            float ej0 = eB[col], ej1 = eB[col + 1];
            float2 t0 = *(const float2*)&aux[(size_t)r0 * NV + col];
            float2 t1 = *(const float2*)&aux[(size_t)r1 * NV + col];
            float c00 = 1.f - __expf(-scale * (1.f - __fdividef(acc[mi][ni][0], ei0 * ej0 + 1e-5f)));
            float c01 = 1.f - __expf(-scale * (1.f - __fdividef(acc[mi][ni][1], ei0 * ej1 + 1e-5f)));
            float c10 = 1.f - __expf(-scale * (1.f - __fdividef(acc[mi][ni][2], ei1 * ej0 + 1e-5f)));
            float c11 = 1.f - __expf(-scale * (1.f - __fdividef(acc[mi][ni][3], ei1 * ej1 + 1e-5f)));
            if (SELF) {
                float m0 = mu[col], m1 = mu[col + 1];
                float d00 = c00 - t0.x, d01 = c01 - t0.y;
                float d10 = c10 - t1.x, d11 = c11 - t1.y;
                sloc += d00 * d00 * __expf(-t0.x) + d01 * d01 * __expf(-t0.y)
                      + d10 * d10 * __expf(-t1.x) + d11 * d11 * __expf(-t1.y);
                f0  += c00 * c00 * m0 + c01 * c01 * m1;
                f1v += c10 * c10 * m0 + c11 * c11 * m1;
                float v00 = c00 - C0F, v01 = c01 - C0F;
                float v10 = c10 - C0F, v11 = c11 - C0F;
                if (r0 == col)     { diag[r0] = v00; v00 = 0.f; }
                if (r0 == col + 1) { diag[r0] = v01; v01 = 0.f; }
                if (r1 == col)     { diag[r1] = v10; v10 = 0.f; }
                if (r1 == col + 1) { diag[r1] = v11; v11 = 0.f; }
                *(bf162*)&cost[(size_t)r0 * NV + col] = __floats2bfloat162_rn(v00, v01);
                *(bf162*)&cost[(size_t)r1 * NV + col] = __floats2bfloat162_rn(v10, v11);
            } else {
                sloc += c00 * t0.x + c01 * t0.y + c10 * t1.x + c11 * t1.y;
            }
        }
        if (SELF) {
            f0  += __shfl_down_sync(0xffffffffu, f0, 1);
            f0  += __shfl_down_sync(0xffffffffu, f0, 2);
            f1v += __shfl_down_sync(0xffffffffu, f1v, 1);
            f1v += __shfl_down_sync(0xffffffffu, f1v, 2);
            if (tig == 0) {
                atomicAdd(&fout[r0], f0);
                atomicAdd(&fout[r1], f1v);
            }
        }
    }

    red[tid] = sloc;
    __syncthreads();
    #pragma unroll
    for (int s = 128; s; s >>= 1) {
        if (tid < s) red[tid] += red[tid + s];
        __syncthreads();
    }
    if (tid == 0) atomicAdd(&g_acc[SELF ? table : 4], (double)red[0]);
}

__global__ void k_orth() {
    int table = blockIdx.y;
    int r = blockIdx.x;
    const float* __restrict__ embs = table ? g_embs2 : g_embs1;
    int t = threadIdx.x;
    float s = 0.f;
    #pragma unroll 4
    for (int k = 0; k < NV; k++)
        s += embs[(size_t)k * DV + r] * embs[(size_t)k * DV + t];
    float v = s - (t == r ? 1.f : 0.f);
    v = v * v;
    __shared__ float red[DV];
    red[t] = v;
    __syncthreads();
    for (int k = DV / 2; k; k >>= 1) {
        if (t < k) red[t] += red[t + k];
        __syncthreads();
    }
    if (t == 0) atomicAdd(&g_acc[2 + table], (double)red[0]);
}

__global__ void k_rowsum(const float* __restrict__ T) {
    int i = blockIdx.x;
    int t = threadIdx.x;
    float s = 0.f;
    for (int j = t; j < NV; j += 256) s += T[(size_t)i * NV + j];
    __shared__ float red[256];
    red[t] = s;
    __syncthreads();
    for (int k = 128; k; k >>= 1) { if (t < k) red[t] += red[t + k]; __syncthreads(); }
    if (t == 0) g_rs[i] = red[0];
}

__global__ void k_colsum(const float* __restrict__ T) {
    int j = blockIdx.x * 256 + threadIdx.x;
    int ibase = blockIdx.y * 256;
    float s = 0.f;
    #pragma unroll 4
    for (int i = 0; i < 256; i++) s += T[(size_t)(ibase + i) * NV + j];
    atomicAdd(&g_csm[j], s);
}

// Rank-one corrections: acc[6] += rs'(Ds rs), acc[7] += csm'(Dt csm).
__global__ void k_gemv() {
    int table = blockIdx.y;
    int row = blockIdx.x;
    const bf16* __restrict__ D = table ? g_ct : g_cs;
    const float* __restrict__ dg = table ? g_db : g_da;
    const float* __restrict__ v = table ? g_csm : g_rs;
    const bf162* __restrict__ Dr = (const bf162*)&D[(size_t)row * NV];
    int t = threadIdx.x;
    float s = 0.f;
    for (int j = t; j < NV / 2; j += 256) {
        bf162 p = Dr[j];
        s += __low2float(p) * v[2 * j] + __high2float(p) * v[2 * j + 1];
    }
    __shared__ float red[256];
    red[t] = s;
    __syncthreads();
    for (int k = 128; k; k >>= 1) { if (t < k) red[t] += red[t + k]; __syncthreads(); }
    if (t == 0)
        atomicAdd(&g_acc[6 + table],
                  ((double)red[0] + (double)dg[row] * (double)v[row]) * (double)v[row]);
}

// Transpose trans -> g_Tt (bf16), 32x32 tiles.
__global__ void k_transpose(const float* __restrict__ T) {
    __shared__ float tile[32][33];
    int x = blockIdx.x * 32 + threadIdx.x;
    int y0 = blockIdx.y * 32;
    #pragma unroll
    for (int j = 0; j < 4; j++)
        tile[threadIdx.y + 8 * j][threadIdx.x] = T[(size_t)(y0 + threadIdx.y + 8 * j) * NV + x];
    __syncthreads();
    int xo = blockIdx.y * 32 + threadIdx.x;
    int yo0 = blockIdx.x * 32;
    #pragma unroll
    for (int j = 0; j < 4; j++)
        g_Tt[(size_t)(yo0 + threadIdx.y + 8 * j) * NV + xo] =
            __float2bfloat16(tile[threadIdx.x][threadIdx.y + 8 * j]);
}

// ---------------------------------------------------------------------------
// bf16 mma.sync GEMM: CTA 128x128, BK=32 bf16, 4-stage cp.async pipeline,
// ldmatrix.x4 fragment loads (stride 80B => LDSM phases conflict-free).
// FUSE=false: X = As@Tt-tensor + diag(a)T fp32; store bf16; acc[8] += T∘X·b.
// FUSE=true:  acc[5] += <(X @ Bs), T>.
// ---------------------------------------------------------------------------
constexpr int BKC = 32;
constexpr int NCH = NV / BKC;          // 128
constexpr int SROW = 80;               // bytes per smem row
constexpr int TILEB = 128 * SROW;      // 10240
constexpr int STAGEB = 2 * TILEB;      // 20480
constexpr int NSTG = 4;
constexpr uint32_t G_SMEM = NSTG * STAGEB;   // 81920

template<bool FUSE>
__global__ __launch_bounds__(256, 2) void k_mmagemm(const float* __restrict__ T) {
    const bf16* __restrict__ A = FUSE ? g_X : g_cs;
    const bf16* __restrict__ B = FUSE ? g_ct : g_Tt;

    extern __shared__ char sm[];
    const uint32_t smb = smem_u32(sm);
    int tid = threadIdx.x, wid = tid >> 5, lane = tid & 31;
    int m0 = blockIdx.y * 128, n0 = blockIdx.x * 128;
    int wm = wid >> 2, wn = wid & 3;
    int g = lane >> 2, tig = lane & 3;

    // ldmatrix per-lane base offsets within a tile
    // A x4 (16x16): lanes 0-7 m0(rows+0..7,kLow) 8-15 m1(rows+8..15,kLow)
    //               16-23 m2(kHigh) 24-31 m3(kHigh)
    const uint32_t aoff = (uint32_t)((wm * 64 + (lane & 15)) * SROW + ((lane >> 4) * 16));
    // B x4 covering 16 n-rows: m0(n+0..7,kLow) m1(n+0..7,kHigh) m2(n+8..15,kLow) m3(n+8..15,kHigh)
    const uint32_t boff = (uint32_t)((wn * 32 + (lane & 7) + ((lane & 16) >> 1)) * SROW
                                     + ((lane & 8) << 1));

    float acc[4][4][4];
    #pragma unroll
    for (int mi = 0; mi < 4; mi++)
        #pragma unroll
        for (int ni = 0; ni < 4; ni++)
            #pragma unroll
            for (int q = 0; q < 4; q++) acc[mi][ni][q] = 0.f;

    auto load_chunk = [&](int s, int k0) {
        uint32_t base = smb + (uint32_t)(s * STAGEB);
        #pragma unroll
        for (int q = 0; q < 4; q++) {
            int idx = tid + 256 * q;
            int isB = idx >> 9;
            int id = idx & 511;
            int row = id >> 2, seg = id & 3;
            const bf16* src = isB ? &B[(size_t)(n0 + row) * NV + k0 + seg * 8]
                                  : &A[(size_t)(m0 + row) * NV + k0 + seg * 8];
            uint32_t dst = base + (uint32_t)(isB * TILEB + row * SROW + seg * 16);
            CP16(dst, src);
        }
    };

    #pragma unroll
    for (int s = 0; s < NSTG; s++) { load_chunk(s, s * BKC); CP_COMMIT(); }

    #pragma unroll 1
    for (int c = 0; c < NCH; c++) {
        int s = c & (NSTG - 1);
        CP_WAIT3();
        __syncthreads();
        uint32_t aBase = smb + (uint32_t)(s * STAGEB) + aoff;
        uint32_t bBase = smb + (uint32_t)(s * STAGEB + TILEB) + boff;
        #pragma unroll
        for (int ks = 0; ks < 2; ks++) {
            uint32_t kb = ks * 32;
            uint32_t afr[4][4], bfr[2][4];
            #pragma unroll
            for (int mi = 0; mi < 4; mi++)
                ldsm_x4(afr[mi], aBase + mi * (16 * SROW) + kb);
            #pragma unroll
            for (int np = 0; np < 2; np++)
                ldsm_x4(bfr[np], bBase + np * (16 * SROW) + kb);
            #pragma unroll
            for (int mi = 0; mi < 4; mi++)
                #pragma unroll
                for (int ni = 0; ni < 4; ni++)
                    mma_bf16(acc[mi][ni], afr[mi], &bfr[ni >> 1][(ni & 1) * 2]);
        }
        __syncthreads();
        if (c + NSTG < NCH) load_chunk(s, (c + NSTG) * BKC);
        CP_COMMIT();
    }

    float loc = 0.f;   // !FUSE: sum T∘X·b ;  FUSE: sum (X@Bs)∘T
    if (!FUSE) {
        #pragma unroll
        for (int mi = 0; mi < 4; mi++) {
            int r0 = m0 + wm * 64 + mi * 16 + g;
            int r1 = r0 + 8;
            float da0 = g_da[r0], da1 = g_da[r1];
            #pragma unroll
            for (int ni = 0; ni < 4; ni++) {
                int col = n0 + wn * 32 + ni * 8 + 2 * tig;
                float2 t0 = *(const float2*)&T[(size_t)r0 * NV + col];
                float2 t1 = *(const float2*)&T[(size_t)r1 * NV + col];
                float db0 = g_db[col], db1 = g_db[col + 1];
                float x00 = acc[mi][ni][0] + da0 * t0.x;
                float x01 = acc[mi][ni][1] + da0 * t0.y;
                float x10 = acc[mi][ni][2] + da1 * t1.x;
                float x11 = acc[mi][ni][3] + da1 * t1.y;
                loc += t0.x * x00 * db0 + t0.y * x01 * db1
                     + t1.x * x10 * db0 + t1.y * x11 * db1;
                *(bf162*)&g_X[(size_t)r0 * NV + col] = __floats2bfloat162_rn(x00, x01);
                *(bf162*)&g_X[(size_t)r1 * NV + col] = __floats2bfloat162_rn(x10, x11);
            }
        }
    } else {
        #pragma unroll
        for (int mi = 0; mi < 4; mi++) {
            int r0 = m0 + wm * 64 + mi * 16 + g;
            int r1 = r0 + 8;
            #pragma unroll
            for (int ni = 0; ni < 4; ni++) {
                int col = n0 + wn * 32 + ni * 8 + 2 * tig;
                float2 t0 = *(const float2*)&T[(size_t)r0 * NV + col];
                float2 t1 = *(const float2*)&T[(size_t)r1 * NV + col];
                loc += acc[mi][ni][0] * t0.x + acc[mi][ni][1] * t0.y
                     + acc[mi][ni][2] * t1.x + acc[mi][ni][3] * t1.y;
            }
        }
    }

    __syncthreads();
    float* red = (float*)sm;
    red[tid] = loc;
    __syncthreads();
    #pragma unroll
    for (int s = 128; s; s >>= 1) {
        if (tid < s) red[tid] += red[tid + s];
        __syncthreads();
    }
    if (tid == 0) atomicAdd(&g_acc[FUSE ? 5 : 8], (double)red[0]);
}

__global__ void k_finalize(float* __restrict__ out) {
    __shared__ double sd[256];
    __shared__ double ss[256];
    int t = threadIdx.x;
    double s = 0.0, sum_rs = 0.0;
    for (int i = t; i < NV; i += 256) {
        s += (double)g_f1[i] * (double)g_rs[i] + (double)g_f2[i] * (double)g_csm[i];
        sum_rs += (double)g_rs[i];
    }
    sd[t] = s; ss[t] = sum_rs;
    __syncthreads();
    for (int k = 128; k; k >>= 1) {
        if (t < k) { sd[t] += sd[t + k]; ss[t] += ss[t + k]; }
        __syncthreads();
    }
    if (t == 0) {
        const double c0 = (double)C0F;
        double S = ss[0];
        double inner = c0 * c0 * S * S + c0 * (g_acc[6] + g_acc[7])
                     + g_acc[5] + g_acc[8];
        out[0] = (float)(sd[0] - 2.0 * inner);
        out[1] = (float)g_acc[4];
        out[2] = (float)(g_acc[0] + g_acc[1] + g_acc[2] + g_acc[3]);
    }
}

// ---------------------------------------------------------------------------
extern "C" void kernel_launch(void* const* d_in, const int* in_sizes, int n_in,
                              void* d_out, int out_size) {
    const int*   index1 = (const int*)d_in[0];
    const int*   index2 = (const int*)d_in[1];
    const float* trans  = (const float*)d_in[2];
    const float* mu_s   = (const float*)d_in[3];
    const float* mu_t   = (const float*)d_in[4];
    const float* cost1  = (const float*)d_in[5];
    const float* cost2  = (const float*)d_in[6];
    const float* emb1_w = (const float*)d_in[7];
    const float* emb2_w = (const float*)d_in[8];
    float* out = (float*)d_out;

    cudaFuncSetAttribute(k_mmagemm<false>, cudaFuncAttributeMaxDynamicSharedMemorySize, G_SMEM);
    cudaFuncSetAttribute(k_mmagemm<true>,  cudaFuncAttributeMaxDynamicSharedMemorySize, G_SMEM);

    dim3 g64(NV / 64, NV / 64);
    dim3 gtc(NV / 128, NV / 128);

    k_init<<<NV / 256, 256>>>();
    k_gather<<<2 * NV, DV>>>(index1, index2, emb1_w, emb2_w);
    k_transpose<<<dim3(NV / 32, NV / 32), dim3(32, 8)>>>(trans);
    k_cost_mma<true><<<g64, 256>>>(0, cost1, mu_s);
    k_cost_mma<true><<<g64, 256>>>(1, cost2, mu_t);
    k_mmagemm<false><<<gtc, 256, G_SMEM>>>(trans);        // X = Ds@T (+acc[8])
    k_cost_mma<false><<<g64, 256>>>(0, trans, nullptr);   // d_w fused
    k_orth<<<dim3(DV, 2), DV>>>();
    k_rowsum<<<NV, 256>>>(trans);
    k_colsum<<<dim3(NV / 256, NV / 256), 256>>>(trans);
    k_gemv<<<dim3(NV, 2), 256>>>();
    k_mmagemm<true><<<gtc, 256, G_SMEM>>>(trans);         // <T, X@Bs> -> acc[5]
    k_finalize<<<1, 256>>>(out);
}

// round 8
// speedup vs baseline: 1.0229x; 1.0229x over previous
#include <cuda_runtime.h>
#include <cuda_bf16.h>
#include <cuda_fp16.h>
#include <cstdint>

// ---------------------------------------------------------------------------
// GromovWassersteinEmbedding — GB300 sm_103a (target sm_103 => mma.sync path)
//
//   d_gw = f1·rs + f2·csm - 2*<T, Cs T Ct>
//   Cs = c0·J + diag(a) + As,  Ct = c0·J + diag(b) + Bs   (As,Bs fp8 off-diag)
//   <T,CsTCt> = c0²S² + c0·rsᵀDs rs + c0·csmᵀDt csm + <T, Ds T Dt>
//   X = Ds T = (As@T)_fp8-tensor + diag(a)·T (fp32 epilogue)
//   <T, Ds T Dt> = <T, X@Bs> (GEMM2 fused) + Σ T∘X·b (GEMM1 epilogue)
//   GEMMs in e4m3 (m16n8k32) with static scales: Ds,Dt ×2^7, T ×2^23, X ×2^20.
//   d_w = sum(cost_st .* T) fused;  reg = sims + orths.
// ---------------------------------------------------------------------------

using bf16 = __nv_bfloat16;

constexpr int NV = 4096;
constexpr int DV = 128;
constexpr float C0F = 0.99326205f;       // ~ 1 - exp(-5); identity exact for any c0
constexpr float SC_D = 128.f;            // 2^7
constexpr float SC_T = 8388608.f;        // 2^23
constexpr float SC_X = 1048576.f;        // 2^20
constexpr float INV_G1 = 1.f / (SC_D * SC_T);  // 2^-30
constexpr float INV_G2 = 1.f / (SC_X * SC_D);  // 2^-27

__device__ float   g_embs1[NV * DV];
__device__ float   g_embs2[NV * DV];
__device__ bf16    g_eh1[NV * DV];           // bf16 embs for gram mma
__device__ bf16    g_eh2[NV * DV];
__device__ float   g_e1[NV];
__device__ float   g_e2[NV];
__device__ uint8_t g_cs8[(size_t)NV * NV];   // As × 2^7 (e4m3, off-diag)
__device__ uint8_t g_ct8[(size_t)NV * NV];   // Bs × 2^7
__device__ uint8_t g_Tt8[(size_t)NV * NV];   // trans^T × 2^23
__device__ uint8_t g_X8 [(size_t)NV * NV];   // X × 2^20
__device__ float   g_da[NV];                 // diag of Ds (fp32)
__device__ float   g_db[NV];                 // diag of Dt
__device__ float   g_f1[NV];
__device__ float   g_f2[NV];
__device__ float   g_rs[NV];
__device__ float   g_csm[NV];
__device__ double  g_acc[16];
// acc: 0 reg_s, 1 reg_t, 2 orth1, 3 orth2, 4 d_w, 5 <T, X@Bs>,
//      6 rs'Ds rs, 7 csm'Dt csm, 8 sum T∘X·b

// ------------------------------- helpers -----------------------------------
__device__ __forceinline__ uint32_t smem_u32(const void* p) {
    uint32_t a;
    asm("{ .reg .u64 t; cvta.to.shared.u64 t, %1; cvt.u32.u64 %0, t; }" : "=r"(a) : "l"(p));
    return a;
}
#define CP16(dst, src) \
    asm volatile("cp.async.cg.shared.global [%0], [%1], 16;" :: "r"(dst), "l"(src))
#define CP_COMMIT() asm volatile("cp.async.commit_group;" ::: "memory")
#define CP_WAIT3()  asm volatile("cp.async.wait_group 3;" ::: "memory")

__device__ __forceinline__ void mma_bf16(float c[4], const uint32_t a[4], const uint32_t b[2]) {
    asm volatile("mma.sync.aligned.m16n8k16.row.col.f32.bf16.bf16.f32 "
                 "{%0,%1,%2,%3}, {%4,%5,%6,%7}, {%8,%9}, {%0,%1,%2,%3};"
                 : "+f"(c[0]), "+f"(c[1]), "+f"(c[2]), "+f"(c[3])
                 : "r"(a[0]), "r"(a[1]), "r"(a[2]), "r"(a[3]),
                   "r"(b[0]), "r"(b[1]));
}
__device__ __forceinline__ void mma_fp8(float c[4], const uint32_t a[4], const uint32_t b[2]) {
    asm volatile("mma.sync.aligned.m16n8k32.row.col.f32.e4m3.e4m3.f32 "
                 "{%0,%1,%2,%3}, {%4,%5,%6,%7}, {%8,%9}, {%0,%1,%2,%3};"
                 : "+f"(c[0]), "+f"(c[1]), "+f"(c[2]), "+f"(c[3])
                 : "r"(a[0]), "r"(a[1]), "r"(a[2]), "r"(a[3]),
                   "r"(b[0]), "r"(b[1]));
}
// low byte <- lo, high byte <- hi
__device__ __forceinline__ uint16_t pack_e4m3(float lo, float hi) {
    uint16_t p;
    asm("cvt.rn.satfinite.e4m3x2.f32 %0, %1, %2;" : "=h"(p) : "f"(hi), "f"(lo));
    return p;
}
// 2 e4m3 -> 2 floats
__device__ __forceinline__ float2 unpack_e4m3(uint16_t v) {
    uint32_t h2;
    asm("cvt.rn.f16x2.e4m3x2 %0, %1;" : "=r"(h2) : "h"(v));
    __half2 h = *(__half2*)&h2;
    return __half22float2(h);
}

// ---------------------------------------------------------------------------
__global__ void k_init() {
    int i = blockIdx.x * blockDim.x + threadIdx.x;
    if (i < NV) { g_f1[i] = 0.f; g_f2[i] = 0.f; g_csm[i] = 0.f; }
    if (i < 16) g_acc[i] = 0.0;
}

__global__ void k_gather(const int* __restrict__ idx1, const int* __restrict__ idx2,
                         const float* __restrict__ w1, const float* __restrict__ w2) {
    int b = blockIdx.x;
    int table = b >> 12;
    int row = b & (NV - 1);
    const int* __restrict__ idx = table ? idx2 : idx1;
    const float* __restrict__ w = table ? w2 : w1;
    float* embs = table ? g_embs2 : g_embs1;
    bf16* embh = table ? g_eh2 : g_eh1;
    float* e = table ? g_e2 : g_e1;
    int t = threadIdx.x;
    float v = w[(size_t)idx[row] * DV + t];
    embs[row * DV + t] = v;
    embh[row * DV + t] = __float2bfloat16(v);
    float s = v * v;
    #pragma unroll
    for (int o = 16; o; o >>= 1) s += __shfl_down_sync(0xffffffffu, s, o);
    __shared__ float ws[4];
    if ((t & 31) == 0) ws[t >> 5] = s;
    __syncthreads();
    if (t == 0) e[row] = sqrtf(ws[0] + ws[1] + ws[2] + ws[3]);
}

// ---------------------------------------------------------------------------
// Cost kernels with tensor-core gram: 64x64 tile/block, 8 warps (2m x 4n).
// SELF: writes Ds/Dt as e4m3 × 2^7 (off-diag), fp32 diag, + reductions.
// ---------------------------------------------------------------------------
template<bool SELF>
__global__ __launch_bounds__(256) void k_cost_mma(int table,
        const float* __restrict__ aux, const float* __restrict__ mu) {
    const bf16* __restrict__ embA = (SELF && table) ? g_eh2 : g_eh1;
    const bf16* __restrict__ embB = SELF ? embA : g_eh2;
    const float* __restrict__ eA  = (SELF && table) ? g_e2 : g_e1;
    const float* __restrict__ eB  = SELF ? eA : g_e2;
    uint8_t* __restrict__ cost = table ? g_ct8 : g_cs8;
    float* __restrict__ diag = table ? g_db : g_da;
    float* __restrict__ fout = table ? g_f2 : g_f1;

    __shared__ __align__(16) char smA[64 * 272];
    __shared__ __align__(16) char smB[64 * 272];
    __shared__ float red[256];

    int tid = threadIdx.x, wid = tid >> 5, lane = tid & 31;
    int g = lane >> 2, tig = lane & 3;
    int wm = wid >> 2, wn = wid & 3;
    int i0 = blockIdx.y * 64, j0 = blockIdx.x * 64;

    #pragma unroll
    for (int q = 0; q < 4; q++) {
        int idx = tid + 256 * q;
        int row = idx >> 4, c16 = idx & 15;
        *(uint4*)(smA + row * 272 + c16 * 16) =
            *(const uint4*)&embA[(size_t)(i0 + row) * DV + c16 * 8];
        *(uint4*)(smB + row * 272 + c16 * 16) =
            *(const uint4*)&embB[(size_t)(j0 + row) * DV + c16 * 8];
    }
    __syncthreads();

    float acc[2][2][4];
    #pragma unroll
    for (int mi = 0; mi < 2; mi++)
        #pragma unroll
        for (int ni = 0; ni < 2; ni++)
            #pragma unroll
            for (int q = 0; q < 4; q++) acc[mi][ni][q] = 0.f;

    #pragma unroll
    for (int k = 0; k < 8; k++) {
        int kb = k * 32;
        uint32_t afr[2][4], bfr[2][2];
        #pragma unroll
        for (int mi = 0; mi < 2; mi++) {
            const char* ar0 = smA + (wm * 32 + mi * 16 + g) * 272 + kb + tig * 4;
            const char* ar1 = ar0 + 8 * 272;
            afr[mi][0] = *(const uint32_t*)ar0;
            afr[mi][1] = *(const uint32_t*)ar1;
            afr[mi][2] = *(const uint32_t*)(ar0 + 16);
            afr[mi][3] = *(const uint32_t*)(ar1 + 16);
        }
        #pragma unroll
        for (int ni = 0; ni < 2; ni++) {
            const char* br = smB + (wn * 16 + ni * 8 + g) * 272 + kb + tig * 4;
            bfr[ni][0] = *(const uint32_t*)br;
            bfr[ni][1] = *(const uint32_t*)(br + 16);
        }
        #pragma unroll
        for (int mi = 0; mi < 2; mi++)
            #pragma unroll
            for (int ni = 0; ni < 2; ni++)
                mma_bf16(acc[mi][ni], afr[mi], bfr[ni]);
    }

    const float scale = SELF ? 5.0f : 1.0f;
    float sloc = 0.f;
    #pragma unroll
    for (int mi = 0; mi < 2; mi++) {
        int r0 = i0 + wm * 32 + mi * 16 + g;
        int r1 = r0 + 8;
        float ei0 = eA[r0], ei1 = eA[r1];
        float f0 = 0.f, f1v = 0.f;
        #pragma unroll
        for (int ni = 0; ni < 2; ni++) {
            int col = j0 + wn * 16 + ni * 8 + 2 * tig;
            float ej0 = eB[col], ej1 = eB[col + 1];
            float2 t0 = *(const float2*)&aux[(size_t)r0 * NV + col];
            float2 t1 = *(const float2*)&aux[(size_t)r1 * NV + col];
            float c00 = 1.f - __expf(-scale * (1.f - __fdividef(acc[mi][ni][0], ei0 * ej0 + 1e-5f)));
            float c01 = 1.f - __expf(-scale * (1.f - __fdividef(acc[mi][ni][1], ei0 * ej1 + 1e-5f)));
            float c10 = 1.f - __expf(-scale * (1.f - __fdividef(acc[mi][ni][2], ei1 * ej0 + 1e-5f)));
            float c11 = 1.f - __expf(-scale * (1.f - __fdividef(acc[mi][ni][3], ei1 * ej1 + 1e-5f)));
            if (SELF) {
                float m0 = mu[col], m1 = mu[col + 1];
                float d00 = c00 - t0.x, d01 = c01 - t0.y;
                float d10 = c10 - t1.x, d11 = c11 - t1.y;
                sloc += d00 * d00 * __expf(-t0.x) + d01 * d01 * __expf(-t0.y)
                      + d10 * d10 * __expf(-t1.x) + d11 * d11 * __expf(-t1.y);
                f0  += c00 * c00 * m0 + c01 * c01 * m1;
                f1v += c10 * c10 * m0 + c11 * c11 * m1;
                float v00 = c00 - C0F, v01 = c01 - C0F;
                float v10 = c10 - C0F, v11 = c11 - C0F;
                if (r0 == col)     { diag[r0] = v00; v00 = 0.f; }
                if (r0 == col + 1) { diag[r0] = v01; v01 = 0.f; }
                if (r1 == col)     { diag[r1] = v10; v10 = 0.f; }
                if (r1 == col + 1) { diag[r1] = v11; v11 = 0.f; }
                *(uint16_t*)&cost[(size_t)r0 * NV + col] = pack_e4m3(v00 * SC_D, v01 * SC_D);
                *(uint16_t*)&cost[(size_t)r1 * NV + col] = pack_e4m3(v10 * SC_D, v11 * SC_D);
            } else {
                sloc += c00 * t0.x + c01 * t0.y + c10 * t1.x + c11 * t1.y;
            }
        }
        if (SELF) {
            f0  += __shfl_down_sync(0xffffffffu, f0, 1);
            f0  += __shfl_down_sync(0xffffffffu, f0, 2);
            f1v += __shfl_down_sync(0xffffffffu, f1v, 1);
            f1v += __shfl_down_sync(0xffffffffu, f1v, 2);
            if (tig == 0) {
                atomicAdd(&fout[r0], f0);
                atomicAdd(&fout[r1], f1v);
            }
        }
    }

    red[tid] = sloc;
    __syncthreads();
    #pragma unroll
    for (int s = 128; s; s >>= 1) {
        if (tid < s) red[tid] += red[tid + s];
        __syncthreads();
    }
    if (tid == 0) atomicAdd(&g_acc[SELF ? table : 4], (double)red[0]);
}

__global__ void k_orth() {
    int table = blockIdx.y;
    int r = blockIdx.x;
    const float* __restrict__ embs = table ? g_embs2 : g_embs1;
    int t = threadIdx.x;
    float s = 0.f;
    #pragma unroll 4
    for (int k = 0; k < NV; k++)
        s += embs[(size_t)k * DV + r] * embs[(size_t)k * DV + t];
    float v = s - (t == r ? 1.f : 0.f);
    v = v * v;
    __shared__ float red[DV];
    red[t] = v;
    __syncthreads();
    for (int k = DV / 2; k; k >>= 1) {
        if (t < k) red[t] += red[t + k];
        __syncthreads();
    }
    if (t == 0) atomicAdd(&g_acc[2 + table], (double)red[0]);
}

__global__ void k_rowsum(const float* __restrict__ T) {
    int i = blockIdx.x;
    int t = threadIdx.x;
    float s = 0.f;
    for (int j = t; j < NV; j += 256) s += T[(size_t)i * NV + j];
    __shared__ float red[256];
    red[t] = s;
    __syncthreads();
    for (int k = 128; k; k >>= 1) { if (t < k) red[t] += red[t + k]; __syncthreads(); }
    if (t == 0) g_rs[i] = red[0];
}

__global__ void k_colsum(const float* __restrict__ T) {
    int j = blockIdx.x * 256 + threadIdx.x;
    int ibase = blockIdx.y * 256;
    float s = 0.f;
    #pragma unroll 4
    for (int i = 0; i < 256; i++) s += T[(size_t)(ibase + i) * NV + j];
    atomicAdd(&g_csm[j], s);
}

// Rank-one corrections from the SAME fp8 matrices the GEMMs use (+ fp32 diag).
__global__ void k_gemv() {
    int table = blockIdx.y;
    int row = blockIdx.x;
    const uint8_t* __restrict__ D = table ? g_ct8 : g_cs8;
    const float* __restrict__ dg = table ? g_db : g_da;
    const float* __restrict__ v = table ? g_csm : g_rs;
    const uint32_t* __restrict__ Dr = (const uint32_t*)&D[(size_t)row * NV];
    int t = threadIdx.x;
    float s = 0.f;
    for (int j = t; j < NV / 4; j += 256) {
        uint32_t q = Dr[j];
        float2 p0 = unpack_e4m3((uint16_t)(q & 0xFFFF));
        float2 p1 = unpack_e4m3((uint16_t)(q >> 16));
        s += p0.x * v[4 * j] + p0.y * v[4 * j + 1]
           + p1.x * v[4 * j + 2] + p1.y * v[4 * j + 3];
    }
    __shared__ float red[256];
    red[t] = s;
    __syncthreads();
    for (int k = 128; k; k >>= 1) { if (t < k) red[t] += red[t + k]; __syncthreads(); }
    if (t == 0)
        atomicAdd(&g_acc[6 + table],
                  ((double)red[0] * (1.0 / 128.0) + (double)dg[row] * (double)v[row])
                  * (double)v[row]);
}

// Transpose trans -> g_Tt8 (e4m3 × 2^23), 32x32 tiles.
__global__ void k_transpose(const float* __restrict__ T) {
    __shared__ float tile[32][33];
    int x = blockIdx.x * 32 + threadIdx.x;
    int y0 = blockIdx.y * 32;
    #pragma unroll
    for (int j = 0; j < 4; j++)
        tile[threadIdx.y + 8 * j][threadIdx.x] = T[(size_t)(y0 + threadIdx.y + 8 * j) * NV + x];
    __syncthreads();
    int xo = blockIdx.y * 32 + threadIdx.x;
    int yo0 = blockIdx.x * 32;
    #pragma unroll
    for (int j = 0; j < 4; j++) {
        uint16_t p = pack_e4m3(tile[threadIdx.x][threadIdx.y + 8 * j] * SC_T, 0.f);
        g_Tt8[(size_t)(yo0 + threadIdx.y + 8 * j) * NV + xo] = (uint8_t)p;
    }
}

// ---------------------------------------------------------------------------
// e4m3 mma.sync GEMM: CTA 128x128, chunk = 64 fp8 elems, 4-stage cp.async.
// 8 warps (2m x 4n), warp tile 64x32 = 4x4 m16n8k32 fragments.
// Smem row = 64 data + 16 pad = 80B => conflict-free 32-bit fragment loads.
// FUSE=false: X = As@Tt (scaled 2^30) -> real + diag(a)T; store X×2^20 fp8;
//             acc[8] += T∘X·b (fp32).
// FUSE=true:  acc[5] += <(X @ Bs), T> (descale 2^-27).
// ---------------------------------------------------------------------------
constexpr int BKC = 64;                // fp8 elements per chunk
constexpr int NCH = NV / BKC;          // 64
constexpr int SROW = 80;               // bytes per smem row
constexpr int TILEB = 128 * SROW;      // 10240
constexpr int STAGEB = 2 * TILEB;      // 20480
constexpr int NSTG = 4;
constexpr uint32_t G_SMEM = NSTG * STAGEB;   // 81920

template<bool FUSE>
__global__ __launch_bounds__(256, 2) void k_mmagemm(const float* __restrict__ T) {
    const uint8_t* __restrict__ A = FUSE ? g_X8 : g_cs8;
    const uint8_t* __restrict__ B = FUSE ? g_ct8 : g_Tt8;

    extern __shared__ char sm[];
    const uint32_t smb = smem_u32(sm);
    int tid = threadIdx.x, wid = tid >> 5, lane = tid & 31;
    int m0 = blockIdx.y * 128, n0 = blockIdx.x * 128;
    int wm = wid >> 2, wn = wid & 3;
    int g = lane >> 2, tig = lane & 3;

    float acc[4][4][4];
    #pragma unroll
    for (int mi = 0; mi < 4; mi++)
        #pragma unroll
        for (int ni = 0; ni < 4; ni++)
            #pragma unroll
            for (int q = 0; q < 4; q++) acc[mi][ni][q] = 0.f;

    auto load_chunk = [&](int s, int k0) {
        uint32_t base = smb + (uint32_t)(s * STAGEB);
        #pragma unroll
        for (int q = 0; q < 4; q++) {
            int idx = tid + 256 * q;           // 0..1023
            int isB = idx >> 9;
            int id = idx & 511;
            int row = id >> 2, seg = id & 3;   // 4 x 16B per 64B row
            const uint8_t* src = isB ? &B[(size_t)(n0 + row) * NV + k0 + seg * 16]
                                     : &A[(size_t)(m0 + row) * NV + k0 + seg * 16];
            uint32_t dst = base + (uint32_t)(isB * TILEB + row * SROW + seg * 16);
            CP16(dst, src);
        }
    };

    #pragma unroll
    for (int s = 0; s < NSTG; s++) { load_chunk(s, s * BKC); CP_COMMIT(); }

    #pragma unroll 1
    for (int c = 0; c < NCH; c++) {
        int s = c & (NSTG - 1);
        CP_WAIT3();
        __syncthreads();
        const char* As = sm + s * STAGEB;
        const char* Bs = As + TILEB;
        #pragma unroll
        for (int ks = 0; ks < 2; ks++) {
            int kb = ks * 32;                  // 32 fp8 per k-step
            uint32_t afr[4][4], bfr[4][2];
            #pragma unroll
            for (int mi = 0; mi < 4; mi++) {
                int rb = wm * 64 + mi * 16;
                const char* ar0 = As + (rb + g) * SROW + kb + tig * 4;
                const char* ar1 = As + (rb + g + 8) * SROW + kb + tig * 4;
                afr[mi][0] = *(const uint32_t*)ar0;
                afr[mi][1] = *(const uint32_t*)ar1;
                afr[mi][2] = *(const uint32_t*)(ar0 + 16);
                afr[mi][3] = *(const uint32_t*)(ar1 + 16);
            }
            #pragma unroll
            for (int ni = 0; ni < 4; ni++) {
                int nb = wn * 32 + ni * 8;
                const char* br = Bs + (nb + g) * SROW + kb + tig * 4;
                bfr[ni][0] = *(const uint32_t*)br;
                bfr[ni][1] = *(const uint32_t*)(br + 16);
            }
            #pragma unroll
            for (int mi = 0; mi < 4; mi++)
                #pragma unroll
                for (int ni = 0; ni < 4; ni++)
                    mma_fp8(acc[mi][ni], afr[mi], bfr[ni]);
        }
        __syncthreads();
        if (c + NSTG < NCH) load_chunk(s, (c + NSTG) * BKC);
        CP_COMMIT();
    }

    float loc = 0.f;   // !FUSE: sum T∘X·b ;  FUSE: sum (X@Bs)∘T (scaled)
    if (!FUSE) {
        #pragma unroll
        for (int mi = 0; mi < 4; mi++) {
            int r0 = m0 + wm * 64 + mi * 16 + g;
            int r1 = r0 + 8;
            float da0 = g_da[r0], da1 = g_da[r1];
            #pragma unroll
            for (int ni = 0; ni < 4; ni++) {
                int col = n0 + wn * 32 + ni * 8 + 2 * tig;
                float2 t0 = *(const float2*)&T[(size_t)r0 * NV + col];
                float2 t1 = *(const float2*)&T[(size_t)r1 * NV + col];
                float db0 = g_db[col], db1 = g_db[col + 1];
                float x00 = acc[mi][ni][0] * INV_G1 + da0 * t0.x;
                float x01 = acc[mi][ni][1] * INV_G1 + da0 * t0.y;
                float x10 = acc[mi][ni][2] * INV_G1 + da1 * t1.x;
                float x11 = acc[mi][ni][3] * INV_G1 + da1 * t1.y;
                loc += t0.x * x00 * db0 + t0.y * x01 * db1
                     + t1.x * x10 * db0 + t1.y * x11 * db1;
                *(uint16_t*)&g_X8[(size_t)r0 * NV + col] = pack_e4m3(x00 * SC_X, x01 * SC_X);
                *(uint16_t*)&g_X8[(size_t)r1 * NV + col] = pack_e4m3(x10 * SC_X, x11 * SC_X);
            }
        }
    } else {
        #pragma unroll
        for (int mi = 0; mi < 4; mi++) {
            int r0 = m0 + wm * 64 + mi * 16 + g;
            int r1 = r0 + 8;
            #pragma unroll
            for (int ni = 0; ni < 4; ni++) {
                int col = n0 + wn * 32 + ni * 8 + 2 * tig;
                float2 t0 = *(const float2*)&T[(size_t)r0 * NV + col];
                float2 t1 = *(const float2*)&T[(size_t)r1 * NV + col];
                loc += acc[mi][ni][0] * t0.x + acc[mi][ni][1] * t0.y
                     + acc[mi][ni][2] * t1.x + acc[mi][ni][3] * t1.y;
            }
        }
    }

    __syncthreads();
    float* red = (float*)sm;
    red[tid] = loc;
    __syncthreads();
    #pragma unroll
    for (int s = 128; s; s >>= 1) {
        if (tid < s) red[tid] += red[tid + s];
        __syncthreads();
    }
    if (tid == 0) {
        double blocksum = (double)red[0];
        if (FUSE) blocksum *= (double)INV_G2;
        atomicAdd(&g_acc[FUSE ? 5 : 8], blocksum);
    }
}

__global__ void k_finalize(float* __restrict__ out) {
    __shared__ double sd[256];
    __shared__ double ss[256];
    int t = threadIdx.x;
    double s = 0.0, sum_rs = 0.0;
    for (int i = t; i < NV; i += 256) {
        s += (double)g_f1[i] * (double)g_rs[i] + (double)g_f2[i] * (double)g_csm[i];
        sum_rs += (double)g_rs[i];
    }
    sd[t] = s; ss[t] = sum_rs;
    __syncthreads();
    for (int k = 128; k; k >>= 1) {
        if (t < k) { sd[t] += sd[t + k]; ss[t] += ss[t + k]; }
        __syncthreads();
    }
    if (t == 0) {
        const double c0 = (double)C0F;
        double S = ss[0];
        double inner = c0 * c0 * S * S + c0 * (g_acc[6] + g_acc[7])
                     + g_acc[5] + g_acc[8];
        out[0] = (float)(sd[0] - 2.0 * inner);
        out[1] = (float)g_acc[4];
        out[2] = (float)(g_acc[0] + g_acc[1] + g_acc[2] + g_acc[3]);
    }
}

// ---------------------------------------------------------------------------
extern "C" void kernel_launch(void* const* d_in, const int* in_sizes, int n_in,
                              void* d_out, int out_size) {
    const int*   index1 = (const int*)d_in[0];
    const int*   index2 = (const int*)d_in[1];
    const float* trans  = (const float*)d_in[2];
    const float* mu_s   = (const float*)d_in[3];
    const float* mu_t   = (const float*)d_in[4];
    const float* cost1  = (const float*)d_in[5];
    const float* cost2  = (const float*)d_in[6];
    const float* emb1_w = (const float*)d_in[7];
    const float* emb2_w = (const float*)d_in[8];
    float* out = (float*)d_out;

    cudaFuncSetAttribute(k_mmagemm<false>, cudaFuncAttributeMaxDynamicSharedMemorySize, G_SMEM);
    cudaFuncSetAttribute(k_mmagemm<true>,  cudaFuncAttributeMaxDynamicSharedMemorySize, G_SMEM);

    dim3 g64(NV / 64, NV / 64);
    dim3 gtc(NV / 128, NV / 128);

    k_init<<<NV / 256, 256>>>();
    k_gather<<<2 * NV, DV>>>(index1, index2, emb1_w, emb2_w);
    k_transpose<<<dim3(NV / 32, NV / 32), dim3(32, 8)>>>(trans);
    k_cost_mma<true><<<g64, 256>>>(0, cost1, mu_s);
    k_cost_mma<true><<<g64, 256>>>(1, cost2, mu_t);
    k_mmagemm<false><<<gtc, 256, G_SMEM>>>(trans);        // X = Ds@T (+acc[8])
    k_cost_mma<false><<<g64, 256>>>(0, trans, nullptr);   // d_w fused
    k_orth<<<dim3(DV, 2), DV>>>();
    k_rowsum<<<NV, 256>>>(trans);
    k_colsum<<<dim3(NV / 256, NV / 256), 256>>>(trans);
    k_gemv<<<dim3(NV, 2), 256>>>();
    k_mmagemm<true><<<gtc, 256, G_SMEM>>>(trans);         // <T, X@Bs> -> acc[5]
    k_finalize<<<1, 256>>>(out);
}